// round 2
// baseline (speedup 1.0000x reference)
#include <cuda_runtime.h>
#include <math.h>

// Problem constants
constexpr int cT = 1024, cS = 1024, cB = 8, cE = 768, cH = 12, cD = 64;
constexpr int TB = cT * cB;        // 8192 rows for the dense GEMMs

// ---------------- scratch (device globals; no allocation allowed) -----------
__device__ float g_q   [cB * cH * cT * cD];            // [B,H,T,D] (pre-scaled)
__device__ float g_k   [cB * cH * cS * cD];            // [B,H,S,D]
__device__ float g_vt  [cB * cH * cD * cS];            // [B,H,D,S] (transposed V)
__device__ float g_L   [(size_t)cB * cH * cT * cS];    // [B,H,T,S] logits -> probs (402MB)
__device__ float g_m   [cB * cH * cT];
__device__ float g_z   [cB * cH * cT];
__device__ float g_attn[cT * cB * cE];                 // [T,B,E] attention output

// ---------------- generic NT SGEMM: C = A(MxK) * W(NxK)^T ------------------
// MODE 0: q = outs  @ Win[0:E]^T   + b, *0.125, scatter to g_q [B,H,T,D]
// MODE 1: k = gs    @ Win[E:2E]^T  + b,          scatter to g_k [B,H,S,D]
// MODE 2: v = gs    @ Win[2E:3E]^T + b,          scatter to g_vt [B,H,D,S]
// MODE 3: L = q @ k^T + attn_mask (+ -inf pad), per (b,h) slice (z = b*H+h)
// MODE 4: O = P @ Vt^T per (b,h) slice -> g_attn [T,B,E]
// MODE 5: x = g_attn @ Wout^T + b_out -> Cout linear [T,B,E]
constexpr int BM = 128, BN = 64, BK = 16, TM = 8, TN = 4;

template <int MODE>
__global__ __launch_bounds__(256)
void sgemm_nt(const float* __restrict__ A, const float* __restrict__ Bw,
              const float* __restrict__ bias, float* __restrict__ Cout,
              const float* __restrict__ amask, const unsigned char* __restrict__ pmask)
{
    constexpr int K = (MODE == 3) ? cD : (MODE == 4 ? cS : cE);
    constexpr int lda = K;
    constexpr int ldb = K;

    const int zb = blockIdx.z;
    const float* Ap;
    const float* Bp;
    if constexpr (MODE <= 2)      { Ap = A;                              Bp = Bw; }
    else if constexpr (MODE == 3) { Ap = g_q + zb * (cT * cD);           Bp = g_k + zb * (cS * cD); }
    else if constexpr (MODE == 4) { Ap = g_L + (size_t)zb * cT * cS;     Bp = g_vt + zb * (cD * cS); }
    else                          { Ap = g_attn;                         Bp = Bw; }

    __shared__ float As[BK][BM];
    __shared__ float Bs[BK][BN];

    const int tid = threadIdx.x;
    const int m0 = blockIdx.y * BM;
    const int n0 = blockIdx.x * BN;

    const int ar = tid >> 1;            // 0..127
    const int ac = (tid & 1) * 8;       // 0 or 8
    const int br = tid >> 2;            // 0..63
    const int bc = (tid & 3) * 4;       // 0,4,8,12

    const int rowg = tid >> 4;          // 0..15
    const int colg = tid & 15;          // 0..15
    const int tm0 = rowg * TM;
    const int tn0 = colg * TN;

    float acc[TM][TN];
#pragma unroll
    for (int i = 0; i < TM; i++)
#pragma unroll
        for (int j = 0; j < TN; j++) acc[i][j] = 0.f;

    const float* Aload = Ap + (size_t)(m0 + ar) * lda + ac;
    const float* Bload = Bp + (size_t)(n0 + br) * ldb + bc;

    for (int k0 = 0; k0 < K; k0 += BK) {
        const float4 a0 = *(const float4*)(Aload + k0);
        const float4 a1 = *(const float4*)(Aload + k0 + 4);
        const float4 b0 = *(const float4*)(Bload + k0);
        __syncthreads();
        As[ac + 0][ar] = a0.x; As[ac + 1][ar] = a0.y;
        As[ac + 2][ar] = a0.z; As[ac + 3][ar] = a0.w;
        As[ac + 4][ar] = a1.x; As[ac + 5][ar] = a1.y;
        As[ac + 6][ar] = a1.z; As[ac + 7][ar] = a1.w;
        Bs[bc + 0][br] = b0.x; Bs[bc + 1][br] = b0.y;
        Bs[bc + 2][br] = b0.z; Bs[bc + 3][br] = b0.w;
        __syncthreads();
#pragma unroll
        for (int kk = 0; kk < BK; kk++) {
            const float4 av0 = *(const float4*)&As[kk][tm0];
            const float4 av1 = *(const float4*)&As[kk][tm0 + 4];
            const float4 bv  = *(const float4*)&Bs[kk][tn0];
            const float a[TM] = {av0.x, av0.y, av0.z, av0.w, av1.x, av1.y, av1.z, av1.w};
            const float b[TN] = {bv.x, bv.y, bv.z, bv.w};
#pragma unroll
            for (int i = 0; i < TM; i++)
#pragma unroll
                for (int j = 0; j < TN; j++) acc[i][j] += a[i] * b[j];
        }
    }

    const float NEG_INF = __int_as_float(0xff800000);
#pragma unroll
    for (int i = 0; i < TM; i++) {
#pragma unroll
        for (int j = 0; j < TN; j++) {
            const int gm = m0 + tm0 + i;
            const int gn = n0 + tn0 + j;
            float v = acc[i][j];
            if constexpr (MODE <= 2) {
                v += bias[gn];
                if constexpr (MODE == 0) v *= 0.125f;  // D^-0.5
                const int t = gm >> 3, b = gm & 7;     // rows are [T,B] flattened
                const int h = gn >> 6, d = gn & 63;
                if constexpr (MODE <= 1) {
                    float* dst = (MODE == 0) ? g_q : g_k;
                    dst[(((b * cH + h) * cT + t) * cD) + d] = v;
                } else {
                    g_vt[(((b * cH + h) * cD + d) * cS) + t] = v;
                }
            } else if constexpr (MODE == 3) {
                const int b = zb / cH;
                v += amask[gm * cS + gn];
                if (pmask[b * cS + gn]) v = NEG_INF;
                g_L[(size_t)zb * cT * cS + (size_t)gm * cS + gn] = v;
            } else if constexpr (MODE == 4) {
                const int b = zb / cH, h = zb % cH;
                g_attn[(gm * cB + b) * cE + h * cD + gn] = v;
            } else {
                Cout[(size_t)gm * cE + gn] = v + bias[gn];
            }
        }
    }
}

// ---------------- row stats: m = max_s L, z = sum_s exp(L - m) -------------
__global__ __launch_bounds__(256)
void stats_kernel()
{
    const int warp = blockIdx.x * 8 + (threadIdx.x >> 5);
    const int lane = threadIdx.x & 31;
    if (warp >= cB * cH * cT) return;
    const float* row = g_L + (size_t)warp * cS;
    float m = __int_as_float(0xff800000);
#pragma unroll 4
    for (int i = lane; i < cS; i += 32) m = fmaxf(m, row[i]);
#pragma unroll
    for (int o = 16; o; o >>= 1) m = fmaxf(m, __shfl_xor_sync(~0u, m, o));
    float z = 0.f;
#pragma unroll 4
    for (int i = lane; i < cS; i += 32) z += __expf(row[i] - m);
#pragma unroll
    for (int o = 16; o; o >>= 1) z += __shfl_xor_sync(~0u, z, o);
    if (lane == 0) { g_m[warp] = m; g_z[warp] = z; }
}

// ------- probs in-place, head-max, BCE sum per (t,b) -> atomicAdd out[b] ----
__global__ __launch_bounds__(256)
void prob_bce_kernel(float* __restrict__ out, const int* __restrict__ target_rel,
                     const float* __restrict__ strategy)
{
    const int t = blockIdx.x, b = blockIdx.y;
    __shared__ float sm[cH], srz[cH];
    if (threadIdx.x < cH) {
        const int r = (b * cH + threadIdx.x) * cT + t;
        sm[threadIdx.x] = g_m[r];
        srz[threadIdx.x] = 1.f / g_z[r];
    }
    __syncthreads();

    float lsum = 0.f;
    for (int s = threadIdx.x; s < cS; s += 256) {
        float aw = 0.f;
#pragma unroll
        for (int h = 0; h < cH; h++) {
            const size_t idx = ((size_t)(b * cH + h) * cT + t) * cS + s;
            const float p = __expf(g_L[idx] - sm[h]) * srz[h];
            g_L[idx] = p;
            aw = fmaxf(aw, p);
        }
        const int rel = target_rel[(t * cB + b) * cS + s];
        if (rel != 0) {
            if (rel != 2) lsum += -fmaxf(logf(aw), -100.f);      // target_arc = 1
            else          lsum += -fmaxf(log1pf(-aw), -100.f);   // target_arc = 0
        }
    }
#pragma unroll
    for (int o = 16; o; o >>= 1) lsum += __shfl_xor_sync(~0u, lsum, o);
    __shared__ float wsum[8];
    if ((threadIdx.x & 31) == 0) wsum[threadIdx.x >> 5] = lsum;
    __syncthreads();
    if (threadIdx.x == 0) {
        float tot = 0.f;
#pragma unroll
        for (int w = 0; w < 8; w++) tot += wsum[w];
        atomicAdd(&out[b], tot * strategy[b]);
    }
}

// ---------------- small helpers --------------------------------------------
__global__ void zero_loss(float* out)
{
    if (threadIdx.x < cB) out[threadIdx.x] = 0.f;
}

__global__ __launch_bounds__(256)
void copy_outs_kernel(float* __restrict__ dst, const float* __restrict__ src)
{
    const int i = blockIdx.x * 256 + threadIdx.x;   // float4 index
    ((float4*)dst)[i] = ((const float4*)src)[i];
}

// ---------------- entry point ----------------------------------------------
extern "C" void kernel_launch(void* const* d_in, const int* in_sizes, int n_in,
                              void* d_out, int out_size)
{
    // metadata order: ids, step, outs, graph_state, graph_padding_mask,
    //                 attn_mask, strategy_id, target_rel, Win, b_in, Wout, b_out
    const float*         outs   = (const float*)d_in[2];
    const float*         gstate = (const float*)d_in[3];
    const unsigned char* pmask  = (const unsigned char*)d_in[4];
    const float*         amask  = (const float*)d_in[5];
    const float*         strat  = (const float*)d_in[6];
    const int*           trel   = (const int*)d_in[7];
    const float*         Win    = (const float*)d_in[8];
    const float*         b_in   = (const float*)d_in[9];
    const float*         Wout   = (const float*)d_in[10];
    const float*         b_out  = (const float*)d_in[11];
    float* out = (float*)d_out;

    // output layout: [arc_loss(8) | outs(T*B*E) | x(T*B*E)]
    float* out_loss = out;
    float* out_copy = out + cB;
    float* out_x    = out + cB + (size_t)cT * cB * cE;

    zero_loss<<<1, 32>>>(out_loss);
    copy_outs_kernel<<<(cT * cB * cE / 4) / 256, 256>>>(out_copy, outs);

    dim3 blk(256);
    dim3 gqkv(cE / BN, TB / BM, 1);                    // (12, 64)
    sgemm_nt<0><<<gqkv, blk>>>(outs,   Win,               b_in,          nullptr, nullptr, nullptr);
    sgemm_nt<1><<<gqkv, blk>>>(gstate, Win + cE * cE,     b_in + cE,     nullptr, nullptr, nullptr);
    sgemm_nt<2><<<gqkv, blk>>>(gstate, Win + 2 * cE * cE, b_in + 2 * cE, nullptr, nullptr, nullptr);

    dim3 glog(cS / BN, cT / BM, cB * cH);              // (16, 8, 96)
    sgemm_nt<3><<<glog, blk>>>(nullptr, nullptr, nullptr, nullptr, amask, pmask);

    stats_kernel<<<(cB * cH * cT) / 8, 256>>>();

    dim3 gbce(cT, cB);
    prob_bce_kernel<<<gbce, 256>>>(out_loss, trel, strat);

    dim3 gpv(cD / BN, cT / BM, cB * cH);               // (1, 8, 96)
    sgemm_nt<4><<<gpv, blk>>>(nullptr, nullptr, nullptr, nullptr, nullptr, nullptr);

    dim3 gout(cE / BN, TB / BM, 1);                    // (12, 64)
    sgemm_nt<5><<<gout, blk>>>(nullptr, Wout, b_out, out_x, nullptr, nullptr);
}

// round 3
// speedup vs baseline: 1.2260x; 1.2260x over previous
#include <cuda_runtime.h>
#include <math.h>

constexpr int cT = 1024, cS = 1024, cB = 8, cE = 768, cH = 12, cD = 64;

// ---------------- scratch (device globals) ----------------------------------
__device__ float g_q   [cB * cH * cT * cD];            // [B,H,T,D] (pre-scaled)
__device__ float g_k   [cB * cH * cS * cD];            // [B,H,S,D]
__device__ float g_v   [cB * cH * cS * cD];            // [B,H,S,D]
__device__ float g_L   [(size_t)cB * cH * cT * cS];    // [B,H,T,S]: e = exp(logit)
__device__ float g_z   [cB * cH * cT];                 // row sums of e
__device__ float g_attn[cT * cB * cE];                 // [T,B,E]

// ---------------- packed f32x2 helpers (FFMA2 path) --------------------------
using u64 = unsigned long long;
__device__ __forceinline__ u64 pk(float x, float y) {
    u64 r; asm("mov.b64 %0, {%1, %2};" : "=l"(r) : "f"(x), "f"(y)); return r;
}
__device__ __forceinline__ u64 pk1(float x) {
    u64 r; asm("mov.b64 %0, {%1, %1};" : "=l"(r) : "f"(x)); return r;
}
__device__ __forceinline__ void fma2(u64& d, u64 a, u64 b) {
    asm("fma.rn.f32x2 %0, %1, %2, %0;" : "+l"(d) : "l"(a), "l"(b));
}
__device__ __forceinline__ float2 upk(u64 v) {
    float2 r; asm("mov.b64 {%0, %1}, %2;" : "=f"(r.x), "=f"(r.y) : "l"(v)); return r;
}

// ---------------- generic NT GEMM with FFMA2 ---------------------------------
// MODE 0: q = outs @ Win[0:E]^T + b, *0.125 -> g_q [B,H,T,D]
// MODE 1: kv = gs @ Win[E:3E]^T + b  (N=1536) -> g_k / g_v [B,H,S,D]
// MODE 3: e = exp(q@k^T + amask [pmask -> 0]) -> g_L; atomicAdd rowsum -> g_z
// MODE 4: O = (e @ v) * rz  per (b,h) slice -> g_attn [T,B,E]  (B transposed in-smem)
// MODE 5: x = g_attn @ Wout^T + b_out -> Cout
template <int MODE, int BM, int BN, int THREADS>
__global__ __launch_bounds__(THREADS, 2)
void gemm_k(const float* __restrict__ A, const float* __restrict__ Bw,
            const float* __restrict__ bias, float* __restrict__ Cout,
            const float* __restrict__ amask, const unsigned char* __restrict__ pmask)
{
    constexpr int K   = (MODE == 3) ? cD : ((MODE == 4) ? cS : cE);
    constexpr int BK  = 8;
    constexpr int AF4 = BM * BK / 4 / THREADS;
    constexpr int BF4 = BN * BK / 4 / THREADS;
    constexpr int CW  = BN / 8;

    const int zb = blockIdx.z;
    const float* Ap; const float* Bp;
    if constexpr (MODE == 0 || MODE == 1) { Ap = A;                            Bp = Bw; }
    else if constexpr (MODE == 3)         { Ap = g_q + zb * (cT * cD);         Bp = g_k + zb * (cS * cD); }
    else if constexpr (MODE == 4)         { Ap = g_L + (size_t)zb * cT * cS;   Bp = g_v + zb * (cS * cD); }
    else                                  { Ap = g_attn;                       Bp = Bw; }

    __shared__ float As[2][BK][BM];
    __shared__ float Bs[2][BK][BN];

    const int tid = threadIdx.x;
    const int m0 = blockIdx.y * BM;
    const int n0 = blockIdx.x * BN;
    const int rowg = tid / CW, colg = tid % CW;
    const int tm0 = rowg * 8, tn0 = colg * 8;

    u64 acc[4][8];
#pragma unroll
    for (int i = 0; i < 4; i++)
#pragma unroll
        for (int j = 0; j < 8; j++) acc[i][j] = 0ull;

    float4 pa[AF4], pb[BF4];

    auto loadT = [&](int k0) {
#pragma unroll
        for (int t = 0; t < AF4; t++) {
            const int idx = tid + t * THREADS;
            const int r = idx / (BK / 4), kc = (idx % (BK / 4)) * 4;
            pa[t] = *(const float4*)(Ap + (size_t)(m0 + r) * K + k0 + kc);
        }
        if constexpr (MODE == 4) {
            // B = v[s,d] (ldv = cD): load [BK s-rows x BN d-cols], transpose into Bs
#pragma unroll
            for (int t = 0; t < BF4; t++) {
                const int idx = tid + t * THREADS;
                const int dr = idx % (BN / 4), sr = idx / (BN / 4);
                pb[t] = *(const float4*)(Bp + (size_t)(k0 + sr) * cD + n0 + dr * 4);
            }
        } else {
#pragma unroll
            for (int t = 0; t < BF4; t++) {
                const int idx = tid + t * THREADS;
                const int r = idx / (BK / 4), kc = (idx % (BK / 4)) * 4;
                pb[t] = *(const float4*)(Bp + (size_t)(n0 + r) * K + k0 + kc);
            }
        }
    };
    auto storeS = [&](int buf) {
#pragma unroll
        for (int t = 0; t < AF4; t++) {
            const int idx = tid + t * THREADS;
            const int r = idx / (BK / 4), kc = (idx % (BK / 4)) * 4;
            As[buf][kc + 0][r] = pa[t].x; As[buf][kc + 1][r] = pa[t].y;
            As[buf][kc + 2][r] = pa[t].z; As[buf][kc + 3][r] = pa[t].w;
        }
        if constexpr (MODE == 4) {
#pragma unroll
            for (int t = 0; t < BF4; t++) {
                const int idx = tid + t * THREADS;
                const int dr = idx % (BN / 4), sr = idx / (BN / 4);
                Bs[buf][sr][dr * 4 + 0] = pb[t].x; Bs[buf][sr][dr * 4 + 1] = pb[t].y;
                Bs[buf][sr][dr * 4 + 2] = pb[t].z; Bs[buf][sr][dr * 4 + 3] = pb[t].w;
            }
        } else {
#pragma unroll
            for (int t = 0; t < BF4; t++) {
                const int idx = tid + t * THREADS;
                const int r = idx / (BK / 4), kc = (idx % (BK / 4)) * 4;
                Bs[buf][kc + 0][r] = pb[t].x; Bs[buf][kc + 1][r] = pb[t].y;
                Bs[buf][kc + 2][r] = pb[t].z; Bs[buf][kc + 3][r] = pb[t].w;
            }
        }
    };
    auto compute = [&](int buf) {
#pragma unroll
        for (int kk = 0; kk < BK; kk++) {
            const float4 av0 = *(const float4*)&As[buf][kk][tm0];
            const float4 av1 = *(const float4*)&As[buf][kk][tm0 + 4];
            const float4 bv0 = *(const float4*)&Bs[buf][kk][tn0];
            const float4 bv1 = *(const float4*)&Bs[buf][kk][tn0 + 4];
            const u64 a2[4] = { pk(av0.x, av0.y), pk(av0.z, av0.w),
                                pk(av1.x, av1.y), pk(av1.z, av1.w) };
            const u64 bb[8] = { pk1(bv0.x), pk1(bv0.y), pk1(bv0.z), pk1(bv0.w),
                                pk1(bv1.x), pk1(bv1.y), pk1(bv1.z), pk1(bv1.w) };
#pragma unroll
            for (int ip = 0; ip < 4; ip++)
#pragma unroll
                for (int j = 0; j < 8; j++) fma2(acc[ip][j], a2[ip], bb[j]);
        }
    };

    loadT(0); storeS(0); __syncthreads();
    int buf = 0;
    for (int k0 = BK; k0 < K; k0 += BK) {
        loadT(k0);
        compute(buf);
        storeS(buf ^ 1);
        __syncthreads();
        buf ^= 1;
    }
    compute(buf);

    float c[8][8];
#pragma unroll
    for (int ip = 0; ip < 4; ip++)
#pragma unroll
        for (int j = 0; j < 8; j++) {
            const float2 t = upk(acc[ip][j]);
            c[2 * ip + 0][j] = t.x;
            c[2 * ip + 1][j] = t.y;
        }

    // ---------------- epilogues ----------------
    if constexpr (MODE == 0) {
        const float4 bs0 = *(const float4*)&bias[n0 + tn0];
        const float4 bs1 = *(const float4*)&bias[n0 + tn0 + 4];
        const int gn = n0 + tn0;
        const int h = gn >> 6, d = gn & 63;
#pragma unroll
        for (int i = 0; i < 8; i++) {
            const int gm = m0 + tm0 + i;
            const int t = gm >> 3, b = gm & 7;
            float4 o0, o1;
            o0.x = (c[i][0] + bs0.x) * 0.125f; o0.y = (c[i][1] + bs0.y) * 0.125f;
            o0.z = (c[i][2] + bs0.z) * 0.125f; o0.w = (c[i][3] + bs0.w) * 0.125f;
            o1.x = (c[i][4] + bs1.x) * 0.125f; o1.y = (c[i][5] + bs1.y) * 0.125f;
            o1.z = (c[i][6] + bs1.z) * 0.125f; o1.w = (c[i][7] + bs1.w) * 0.125f;
            float* dst = g_q + (((size_t)(b * cH + h) * cT + t) * cD) + d;
            *(float4*)dst = o0; *(float4*)(dst + 4) = o1;
        }
    } else if constexpr (MODE == 1) {
        const float4 bs0 = *(const float4*)&bias[n0 + tn0];
        const float4 bs1 = *(const float4*)&bias[n0 + tn0 + 4];
        const int gn = n0 + tn0;
        const bool isV = gn >= cE;
        const int g = isV ? gn - cE : gn;
        const int h = g >> 6, d = g & 63;
        float* base = isV ? g_v : g_k;
#pragma unroll
        for (int i = 0; i < 8; i++) {
            const int gm = m0 + tm0 + i;
            const int s = gm >> 3, b = gm & 7;
            float4 o0, o1;
            o0.x = c[i][0] + bs0.x; o0.y = c[i][1] + bs0.y;
            o0.z = c[i][2] + bs0.z; o0.w = c[i][3] + bs0.w;
            o1.x = c[i][4] + bs1.x; o1.y = c[i][5] + bs1.y;
            o1.z = c[i][6] + bs1.z; o1.w = c[i][7] + bs1.w;
            float* dst = base + (((size_t)(b * cH + h) * cS + s) * cD) + d;
            *(float4*)dst = o0; *(float4*)(dst + 4) = o1;
        }
    } else if constexpr (MODE == 3) {
        const int b = zb / cH;
        const u64 pm8 = *(const u64*)&pmask[(size_t)b * cS + n0 + tn0];
        float rsum[8];
#pragma unroll
        for (int i = 0; i < 8; i++) {
            const int gm = m0 + tm0 + i;
            const float4 am0 = *(const float4*)&amask[(size_t)gm * cS + n0 + tn0];
            const float4 am1 = *(const float4*)&amask[(size_t)gm * cS + n0 + tn0 + 4];
            const float am[8] = {am0.x, am0.y, am0.z, am0.w, am1.x, am1.y, am1.z, am1.w};
            float e[8];
            float rs = 0.f;
#pragma unroll
            for (int j = 0; j < 8; j++) {
                const bool msk = ((pm8 >> (8 * j)) & 255ull) != 0;
                e[j] = msk ? 0.f : __expf(c[i][j] + am[j]);
                rs += e[j];
            }
            rsum[i] = rs;
            float* dst = g_L + (size_t)zb * cT * cS + (size_t)gm * cS + n0 + tn0;
            *(float4*)dst       = make_float4(e[0], e[1], e[2], e[3]);
            *(float4*)(dst + 4) = make_float4(e[4], e[5], e[6], e[7]);
        }
#pragma unroll
        for (int i = 0; i < 8; i++) {
#pragma unroll
            for (int o = 8; o; o >>= 1)
                rsum[i] += __shfl_xor_sync(0xffffffffu, rsum[i], o);
        }
        if (colg == 0) {
#pragma unroll
            for (int i = 0; i < 8; i++)
                atomicAdd(&g_z[zb * cT + m0 + tm0 + i], rsum[i]);
        }
    } else if constexpr (MODE == 4) {
        const int b = zb / cH, h = zb % cH;
#pragma unroll
        for (int i = 0; i < 8; i++) {
            const int gm = m0 + tm0 + i;                 // t
            const float rz = 1.0f / g_z[zb * cT + gm];
            float4 o0, o1;
            o0.x = c[i][0] * rz; o0.y = c[i][1] * rz; o0.z = c[i][2] * rz; o0.w = c[i][3] * rz;
            o1.x = c[i][4] * rz; o1.y = c[i][5] * rz; o1.z = c[i][6] * rz; o1.w = c[i][7] * rz;
            float* dst = g_attn + ((size_t)gm * cB + b) * cE + h * cD + n0 + tn0;
            *(float4*)dst = o0; *(float4*)(dst + 4) = o1;
        }
    } else {  // MODE 5
        const float4 bs0 = *(const float4*)&bias[n0 + tn0];
        const float4 bs1 = *(const float4*)&bias[n0 + tn0 + 4];
#pragma unroll
        for (int i = 0; i < 8; i++) {
            const int gm = m0 + tm0 + i;
            float4 o0, o1;
            o0.x = c[i][0] + bs0.x; o0.y = c[i][1] + bs0.y;
            o0.z = c[i][2] + bs0.z; o0.w = c[i][3] + bs0.w;
            o1.x = c[i][4] + bs1.x; o1.y = c[i][5] + bs1.y;
            o1.z = c[i][6] + bs1.z; o1.w = c[i][7] + bs1.w;
            float* dst = Cout + (size_t)gm * cE + n0 + tn0;
            *(float4*)dst = o0; *(float4*)(dst + 4) = o1;
        }
    }
}

// ------- BCE from e-values: p = e * (1/z), head-max, sum -> atomicAdd out[b] --
__global__ __launch_bounds__(256)
void prob_bce_kernel(float* __restrict__ out, const int* __restrict__ target_rel,
                     const float* __restrict__ strategy)
{
    const int t = blockIdx.x, b = blockIdx.y;
    __shared__ float srz[cH];
    if (threadIdx.x < cH)
        srz[threadIdx.x] = 1.0f / g_z[(b * cH + threadIdx.x) * cT + t];
    __syncthreads();

    float lsum = 0.f;
    for (int s = threadIdx.x; s < cS; s += 256) {
        float aw = 0.f;
#pragma unroll
        for (int h = 0; h < cH; h++) {
            const size_t idx = ((size_t)(b * cH + h) * cT + t) * cS + s;
            aw = fmaxf(aw, g_L[idx] * srz[h]);
        }
        const int rel = target_rel[(t * cB + b) * cS + s];
        if (rel != 0) {
            if (rel != 2) lsum += -fmaxf(logf(aw), -100.f);
            else          lsum += -fmaxf(log1pf(-aw), -100.f);
        }
    }
#pragma unroll
    for (int o = 16; o; o >>= 1) lsum += __shfl_xor_sync(0xffffffffu, lsum, o);
    __shared__ float wsum[8];
    if ((threadIdx.x & 31) == 0) wsum[threadIdx.x >> 5] = lsum;
    __syncthreads();
    if (threadIdx.x == 0) {
        float tot = 0.f;
#pragma unroll
        for (int w = 0; w < 8; w++) tot += wsum[w];
        atomicAdd(&out[b], tot * strategy[b]);
    }
}

// ---------------- small helpers ----------------------------------------------
__global__ void zero_loss(float* out)
{
    if (threadIdx.x < cB) out[threadIdx.x] = 0.f;
}
__global__ __launch_bounds__(256)
void zero_z_kernel()
{
    const int i = blockIdx.x * 256 + threadIdx.x;
    if (i < cB * cH * cT) g_z[i] = 0.f;
}
__global__ __launch_bounds__(256)
void copy_outs_kernel(float* __restrict__ dst, const float* __restrict__ src)
{
    const int i = blockIdx.x * 256 + threadIdx.x;
    ((float4*)dst)[i] = ((const float4*)src)[i];
}

// ---------------- entry point -------------------------------------------------
extern "C" void kernel_launch(void* const* d_in, const int* in_sizes, int n_in,
                              void* d_out, int out_size)
{
    const float*         outs   = (const float*)d_in[2];
    const float*         gstate = (const float*)d_in[3];
    const unsigned char* pmask  = (const unsigned char*)d_in[4];
    const float*         amask  = (const float*)d_in[5];
    const float*         strat  = (const float*)d_in[6];
    const int*           trel   = (const int*)d_in[7];
    const float*         Win    = (const float*)d_in[8];
    const float*         b_in   = (const float*)d_in[9];
    const float*         Wout   = (const float*)d_in[10];
    const float*         b_out  = (const float*)d_in[11];
    float* out = (float*)d_out;

    float* out_loss = out;
    float* out_copy = out + cB;
    float* out_x    = out + cB + (size_t)cT * cB * cE;

    zero_loss<<<1, 32>>>(out_loss);
    zero_z_kernel<<<(cB * cH * cT + 255) / 256, 256>>>();
    copy_outs_kernel<<<(cT * cB * cE / 4) / 256, 256>>>(out_copy, outs);

    // MODE 0: Q projection  [8192 x 768] x [768 x 768]
    gemm_k<0, 128, 128, 256><<<dim3(cE / 128, cT * cB / 128, 1), 256>>>(
        outs, Win, b_in, nullptr, nullptr, nullptr);
    // MODE 1: K+V fused     [8192 x 1536]
    gemm_k<1, 128, 128, 256><<<dim3(2 * cE / 128, cS * cB / 128, 1), 256>>>(
        gstate, Win + cE * cE, b_in + cE, nullptr, nullptr, nullptr);
    // MODE 3: logits -> e, rowsums (96 slices of 1024x1024x64)
    gemm_k<3, 128, 128, 256><<<dim3(cS / 128, cT / 128, cB * cH), 256>>>(
        nullptr, nullptr, nullptr, nullptr, amask, pmask);
    // BCE (reads e + z)
    prob_bce_kernel<<<dim3(cT, cB), 256>>>(out_loss, trel, strat);
    // MODE 4: O = softmax(e) @ V  (96 slices of 1024x64x1024)
    gemm_k<4, 128, 64, 128><<<dim3(1, cT / 128, cB * cH), 128>>>(
        nullptr, nullptr, nullptr, nullptr, nullptr, nullptr);
    // MODE 5: out projection
    gemm_k<5, 128, 128, 256><<<dim3(cE / 128, cT * cB / 128, 1), 256>>>(
        nullptr, Wout, b_out, out_x, nullptr, nullptr);
}